// round 13
// baseline (speedup 1.0000x reference)
#include <cuda_runtime.h>
#include <cuda_bf16.h>
#include <cstdint>

// ---------------------------------------------------------------------------
// CopyNet pointer-generator mix, fused, vocab-chunked, PERSISTENT grid.
//   out[b,t,v] = p_gen[b,t] * (v < V ? dist[b,t,v] : 0)
//              + (1 - p_gen[b,t]) * sum_{s: pointer[b,s]==v} alph[b,s,t]
//
// Proven per-CTA shape (R5): 256 threads, NCHUNK=8 (16.06 KB smem chunk),
// 8 CTAs/SM. New: grid-stride persistent CTAs (1184 = 148 SMs x 8) loop over
// all 16384 (row,chunk) tiles -> one wave instead of ~14, eliminating
// wave-transition + drain/fill overhead. Phase 3 is the simple R5 loop
// (empirically fastest) with __ldcs streaming reads.
// ---------------------------------------------------------------------------

#define NCHUNK    8
#define TPB       256
#define GRID_PERS (148 * 8)

__global__ __launch_bounds__(TPB)
void copynet_fused_persist_kernel(const float* __restrict__ dist,
                                  const float* __restrict__ p_gen,
                                  const float* __restrict__ alph,
                                  const int*   __restrict__ pointer,
                                  float* __restrict__ out,
                                  int V4, int Vext4, int chunk4,
                                  int L_DEC, int L_SRC, int n_tiles)
{
    extern __shared__ float srow[];            // chunk4*4 floats
    float4* s4 = reinterpret_cast<float4*>(srow);

    for (int tile = blockIdx.x; tile < n_tiles; tile += gridDim.x) {
        int row   = tile / NCHUNK;             // b*L_DEC + t
        int chunk = tile - row * NCHUNK;
        int b     = row / L_DEC;
        int t     = row - b * L_DEC;

        int lo = chunk * (chunk4 * 4);         // vocab range [lo, hi)
        int hi = lo + chunk4 * 4;

        float pg    = __ldg(&p_gen[row]);
        float one_m = 1.0f - pg;

        // Phase 1: zero the shared accumulator chunk.
        float4 z = make_float4(0.f, 0.f, 0.f, 0.f);
        for (int i = threadIdx.x; i < chunk4; i += TPB)
            s4[i] = z;
        __syncthreads();

        // Phase 2: scan the row's L_SRC (pointer, alpha) pairs; scatter hits.
        {
            const float* arow = alph + ((size_t)b * L_SRC) * L_DEC + t;
            const int*   prow = pointer + b * L_SRC;
            for (int s = threadIdx.x; s < L_SRC; s += TPB) {
                int p = __ldg(&prow[s]);
                if (p >= lo && p < hi) {
                    float a = __ldg(&arow[(size_t)s * L_DEC]);
                    atomicAdd(&srow[p - lo], one_m * a);
                }
            }
        }
        __syncthreads();

        // Phase 3: fused stream (simple loop; ptxas handles the batching):
        //   out = pg*dist (+ pad zeros) + copyp.
        {
            int base4 = chunk * chunk4;
            const float4* src = reinterpret_cast<const float4*>(dist) + (size_t)row * V4;
            float4*       dst = reinterpret_cast<float4*>(out) + (size_t)row * Vext4 + base4;
            for (int i = threadIdx.x; i < chunk4; i += TPB) {
                float4 c = s4[i];
                int g = base4 + i;
                if (g < V4) {
                    float4 d = __ldcs(&src[g]);
                    c.x = fmaf(pg, d.x, c.x);
                    c.y = fmaf(pg, d.y, c.y);
                    c.z = fmaf(pg, d.z, c.z);
                    c.w = fmaf(pg, d.w, c.w);
                }
                dst[i] = c;
            }
        }
        // Barrier before the next tile re-zeroes srow (phase-3 reads must drain).
        __syncthreads();
    }
}

// Fallback: full-row-in-smem fused kernel (scalar), for odd shapes.
__global__ void copynet_fused_scalar_kernel(const float* __restrict__ dist,
                                            const float* __restrict__ p_gen,
                                            const float* __restrict__ alph,
                                            const int*   __restrict__ pointer,
                                            float* __restrict__ out,
                                            int V, int Vext,
                                            int L_DEC, int L_SRC)
{
    extern __shared__ float srow[];
    int row = blockIdx.x;
    int b   = row / L_DEC;
    int t   = row - b * L_DEC;
    float pg = __ldg(&p_gen[row]);
    float one_m = 1.0f - pg;

    for (int i = threadIdx.x; i < Vext; i += blockDim.x)
        srow[i] = 0.f;
    __syncthreads();

    const float* arow = alph + ((size_t)b * L_SRC) * L_DEC + t;
    const int*   prow = pointer + b * L_SRC;
    for (int s = threadIdx.x; s < L_SRC; s += blockDim.x)
        atomicAdd(&srow[__ldg(&prow[s])], one_m * __ldg(&arow[(size_t)s * L_DEC]));
    __syncthreads();

    for (int i = threadIdx.x; i < Vext; i += blockDim.x) {
        float c = srow[i];
        if (i < V) c = fmaf(pg, __ldg(&dist[(size_t)row * V + i]), c);
        out[(size_t)row * Vext + i] = c;
    }
}

extern "C" void kernel_launch(void* const* d_in, const int* in_sizes, int n_in,
                              void* d_out, int out_size)
{
    // metadata order: dist_t, p_gen, alph_t, batch_vocab, pointer
    const float* dist    = (const float*)d_in[0];
    const float* p_gen   = (const float*)d_in[1];
    const float* alph    = (const float*)d_in[2];
    const int*   pointer = (const int*)d_in[4];
    float*       out     = (float*)d_out;

    int BT    = in_sizes[1];                 // B * L_DEC   (2048)
    int Vext  = in_sizes[3];                 // 32128
    int BS    = in_sizes[4];                 // B * L_SRC   (4096)
    int L_DEC = in_sizes[2] / BS;            // 256
    int B     = BT / L_DEC;                  // 8
    int L_SRC = BS / B;                      // 512
    int V     = in_sizes[0] / BT;            // 32000

    bool vec_ok = (V % 4 == 0) && (Vext % (4 * NCHUNK) == 0);

    if (vec_ok) {
        int V4      = V / 4;
        int Vext4   = Vext / 4;
        int chunk4  = Vext4 / NCHUNK;         // 1004 float4 = 16.06 KB
        int n_tiles = BT * NCHUNK;            // 16384
        size_t smem_bytes = (size_t)chunk4 * 4 * sizeof(float);
        int grid = GRID_PERS;
        if (grid > n_tiles) grid = n_tiles;
        cudaFuncSetAttribute(copynet_fused_persist_kernel,
                             cudaFuncAttributeMaxDynamicSharedMemorySize,
                             (int)smem_bytes);
        copynet_fused_persist_kernel<<<grid, TPB, smem_bytes>>>(
            dist, p_gen, alph, pointer, out,
            V4, Vext4, chunk4, L_DEC, L_SRC, n_tiles);
    } else {
        size_t smem_bytes = (size_t)Vext * sizeof(float);
        cudaFuncSetAttribute(copynet_fused_scalar_kernel,
                             cudaFuncAttributeMaxDynamicSharedMemorySize,
                             (int)smem_bytes);
        copynet_fused_scalar_kernel<<<BT, 1024, smem_bytes>>>(
            dist, p_gen, alph, pointer, out, V, Vext, L_DEC, L_SRC);
    }
}

// round 14
// speedup vs baseline: 1.5457x; 1.5457x over previous
#include <cuda_runtime.h>
#include <cuda_bf16.h>
#include <cstdint>

// ---------------------------------------------------------------------------
// CopyNet pointer-generator mix, fused, vocab-chunked (proven R5 shape).
//   out[b,t,v] = p_gen[b,t] * (v < V ? dist[b,t,v] : 0)
//              + (1 - p_gen[b,t]) * sum_{s: pointer[b,s]==v} alph[b,s,t]
//
// One CTA per (row, chunk): NCHUNK=8, 256 threads, 16.06 KB smem, 8 CTAs/SM.
// R14: instruction-diet phase 3 — packed fma.rn.f32x2 (2 instead of 4 FMAs
// per float4), branch-free loop for the 7/8 chunks fully inside the vocab,
// ulonglong2 views to avoid pack/unpack. Phase 1/2 identical to R5.
// ---------------------------------------------------------------------------

#define NCHUNK 8
#define TPB    256

__device__ __forceinline__ unsigned long long ffma2(unsigned long long a,
                                                    unsigned long long b,
                                                    unsigned long long c)
{
    unsigned long long d;
    asm("fma.rn.f32x2 %0, %1, %2, %3;" : "=l"(d) : "l"(a), "l"(b), "l"(c));
    return d;
}

__global__ __launch_bounds__(TPB)
void copynet_fused_chunk_kernel(const float* __restrict__ dist,
                                const float* __restrict__ p_gen,
                                const float* __restrict__ alph,
                                const int*   __restrict__ pointer,
                                float* __restrict__ out,
                                int V4, int Vext4, int chunk4,
                                int L_DEC, int L_SRC)
{
    extern __shared__ float srow[];            // chunk4*4 floats
    float4* s4 = reinterpret_cast<float4*>(srow);

    int row   = blockIdx.x / NCHUNK;           // b*L_DEC + t
    int chunk = blockIdx.x - row * NCHUNK;
    int b     = row / L_DEC;
    int t     = row - b * L_DEC;

    int lo = chunk * (chunk4 * 4);             // vocab range [lo, hi)
    int hi = lo + chunk4 * 4;

    float pg    = __ldg(&p_gen[row]);
    float one_m = 1.0f - pg;

    // Phase 1: zero the shared accumulator chunk (STS.128).
    float4 z = make_float4(0.f, 0.f, 0.f, 0.f);
    for (int i = threadIdx.x; i < chunk4; i += TPB)
        s4[i] = z;
    __syncthreads();

    // Phase 2: scan the row's L_SRC (pointer, alpha) pairs; scatter hits.
    // (Identical to the 97.6us R5 kernel.)
    {
        const float* arow = alph + ((size_t)b * L_SRC) * L_DEC + t;
        const int*   prow = pointer + b * L_SRC;
        for (int s = threadIdx.x; s < L_SRC; s += TPB) {
            int p = __ldg(&prow[s]);
            if (p >= lo && p < hi) {
                float a = __ldg(&arow[(size_t)s * L_DEC]);
                atomicAdd(&srow[p - lo], one_m * a);
            }
        }
    }
    __syncthreads();

    // Phase 3: fused stream, minimal instruction count.
    //   out = pg*dist (+ pad zeros) + copyp
    {
        int base4 = chunk * chunk4;
        // pg packed as f32x2 {pg, pg}
        unsigned long long pg2;
        asm("mov.b64 %0, {%1, %1};" : "=l"(pg2) : "f"(pg));

        const ulonglong2* src64 =
            reinterpret_cast<const ulonglong2*>(dist) + (size_t)row * V4;
        ulonglong2* dst64 =
            reinterpret_cast<ulonglong2*>(out) + (size_t)row * Vext4 + base4;
        const ulonglong2* s64 = reinterpret_cast<const ulonglong2*>(srow);

        if (base4 + chunk4 <= V4) {
            // Chunk entirely inside the vocab: branch-free stream.
            #pragma unroll 4
            for (int i = threadIdx.x; i < chunk4; i += TPB) {
                ulonglong2 d = __ldg(&src64[base4 + i]);
                ulonglong2 c = s64[i];
                c.x = ffma2(pg2, d.x, c.x);
                c.y = ffma2(pg2, d.y, c.y);
                dst64[i] = c;
            }
        } else {
            // Boundary chunk (contains the zero-pad tail): predicated.
            for (int i = threadIdx.x; i < chunk4; i += TPB) {
                ulonglong2 c = s64[i];
                int g = base4 + i;
                if (g < V4) {
                    ulonglong2 d = __ldg(&src64[g]);
                    c.x = ffma2(pg2, d.x, c.x);
                    c.y = ffma2(pg2, d.y, c.y);
                }
                dst64[i] = c;
            }
        }
    }
}

// Fallback: full-row-in-smem fused kernel (scalar), for odd shapes.
__global__ void copynet_fused_scalar_kernel(const float* __restrict__ dist,
                                            const float* __restrict__ p_gen,
                                            const float* __restrict__ alph,
                                            const int*   __restrict__ pointer,
                                            float* __restrict__ out,
                                            int V, int Vext,
                                            int L_DEC, int L_SRC)
{
    extern __shared__ float srow[];
    int row = blockIdx.x;
    int b   = row / L_DEC;
    int t   = row - b * L_DEC;
    float pg = __ldg(&p_gen[row]);
    float one_m = 1.0f - pg;

    for (int i = threadIdx.x; i < Vext; i += blockDim.x)
        srow[i] = 0.f;
    __syncthreads();

    const float* arow = alph + ((size_t)b * L_SRC) * L_DEC + t;
    const int*   prow = pointer + b * L_SRC;
    for (int s = threadIdx.x; s < L_SRC; s += blockDim.x)
        atomicAdd(&srow[__ldg(&prow[s])], one_m * __ldg(&arow[(size_t)s * L_DEC]));
    __syncthreads();

    for (int i = threadIdx.x; i < Vext; i += blockDim.x) {
        float c = srow[i];
        if (i < V) c = fmaf(pg, __ldg(&dist[(size_t)row * V + i]), c);
        out[(size_t)row * Vext + i] = c;
    }
}

extern "C" void kernel_launch(void* const* d_in, const int* in_sizes, int n_in,
                              void* d_out, int out_size)
{
    // metadata order: dist_t, p_gen, alph_t, batch_vocab, pointer
    const float* dist    = (const float*)d_in[0];
    const float* p_gen   = (const float*)d_in[1];
    const float* alph    = (const float*)d_in[2];
    const int*   pointer = (const int*)d_in[4];
    float*       out     = (float*)d_out;

    int BT    = in_sizes[1];                 // B * L_DEC   (2048)
    int Vext  = in_sizes[3];                 // 32128
    int BS    = in_sizes[4];                 // B * L_SRC   (4096)
    int L_DEC = in_sizes[2] / BS;            // 256
    int B     = BT / L_DEC;                  // 8
    int L_SRC = BS / B;                      // 512
    int V     = in_sizes[0] / BT;            // 32000

    bool vec_ok = (V % 4 == 0) && (Vext % (4 * NCHUNK) == 0);

    if (vec_ok) {
        int V4     = V / 4;
        int Vext4  = Vext / 4;
        int chunk4 = Vext4 / NCHUNK;          // 1004 float4 = 16.06 KB
        size_t smem_bytes = (size_t)chunk4 * 4 * sizeof(float);
        cudaFuncSetAttribute(copynet_fused_chunk_kernel,
                             cudaFuncAttributeMaxDynamicSharedMemorySize,
                             (int)smem_bytes);
        copynet_fused_chunk_kernel<<<BT * NCHUNK, TPB, smem_bytes>>>(
            dist, p_gen, alph, pointer, out, V4, Vext4, chunk4, L_DEC, L_SRC);
    } else {
        size_t smem_bytes = (size_t)Vext * sizeof(float);
        cudaFuncSetAttribute(copynet_fused_scalar_kernel,
                             cudaFuncAttributeMaxDynamicSharedMemorySize,
                             (int)smem_bytes);
        copynet_fused_scalar_kernel<<<BT, 1024, smem_bytes>>>(
            dist, p_gen, alph, pointer, out, V, Vext, L_DEC, L_SRC);
    }
}

// round 15
// speedup vs baseline: 1.8574x; 1.2017x over previous
#include <cuda_runtime.h>
#include <cuda_bf16.h>
#include <cstdint>

// ---------------------------------------------------------------------------
// CopyNet pointer-generator mix — smem-free fused kernel.
//   out[b,t,v] = p_gen[b,t] * (v < V ? dist[b,t,v] : 0)
//              + (1 - p_gen[b,t]) * sum_{s: pointer[b,s]==v} alph[b,s,t]
//
// One CTA per (row, vocab-chunk), NCHUNK=8, 256 threads, NO shared memory.
//   Phase A: stream out = pg*dist (+ pad zeros) for the chunk.
//   Phase B: scan the row's L_SRC pointers; for hits in this chunk,
//            atomicAdd into the just-written (L2-resident) output lines.
// The CTA exclusively owns its output range, so __syncthreads between the
// phases is the only ordering needed. ~64 L2-hit REDs per CTA.
// ---------------------------------------------------------------------------

#define NCHUNK 8
#define TPB    256

__global__ __launch_bounds__(TPB, 8)
void copynet_stream_scatter_kernel(const float* __restrict__ dist,
                                   const float* __restrict__ p_gen,
                                   const float* __restrict__ alph,
                                   const int*   __restrict__ pointer,
                                   float* __restrict__ out,
                                   int V4, int Vext4, int chunk4,
                                   int L_DEC, int L_SRC)
{
    int row   = blockIdx.x / NCHUNK;           // b*L_DEC + t
    int chunk = blockIdx.x - row * NCHUNK;
    int b     = row / L_DEC;
    int t     = row - b * L_DEC;

    int lo = chunk * (chunk4 * 4);             // vocab range [lo, hi)
    int hi = lo + chunk4 * 4;

    float pg    = __ldg(&p_gen[row]);
    float one_m = 1.0f - pg;

    // Phase A: stream this chunk: out = pg*dist, zero in the pad region.
    {
        int base4 = chunk * chunk4;
        const float4* src = reinterpret_cast<const float4*>(dist) + (size_t)row * V4;
        float4*       dst = reinterpret_cast<float4*>(out) + (size_t)row * Vext4 + base4;

        if (base4 + chunk4 <= V4) {
            // Chunk fully inside the vocab: branch-free.
            for (int i = threadIdx.x; i < chunk4; i += TPB) {
                float4 d = __ldg(&src[base4 + i]);
                d.x *= pg; d.y *= pg; d.z *= pg; d.w *= pg;
                dst[i] = d;
            }
        } else {
            // Boundary chunk: pad region gets zeros.
            for (int i = threadIdx.x; i < chunk4; i += TPB) {
                int g = base4 + i;
                float4 d = make_float4(0.f, 0.f, 0.f, 0.f);
                if (g < V4) {
                    d = __ldg(&src[g]);
                    d.x *= pg; d.y *= pg; d.z *= pg; d.w *= pg;
                }
                dst[i] = d;
            }
        }
    }

    // CTA-scope ordering: phase-A stores visible before phase-B RMWs.
    __syncthreads();

    // Phase B: scatter the row's hits into the freshly written (L2-hot) chunk.
    {
        const float* arow = alph + ((size_t)b * L_SRC) * L_DEC + t;
        const int*   prow = pointer + b * L_SRC;
        float* orow = out + (size_t)row * Vext4 * 4;
        for (int s = threadIdx.x; s < L_SRC; s += TPB) {
            int p = __ldg(&prow[s]);
            if (p >= lo && p < hi) {
                float a = __ldg(&arow[(size_t)s * L_DEC]);
                atomicAdd(&orow[p], one_m * a);
            }
        }
    }
}

// Fallback for odd shapes: full-row smem accumulator (proven correct).
__global__ void copynet_fused_scalar_kernel(const float* __restrict__ dist,
                                            const float* __restrict__ p_gen,
                                            const float* __restrict__ alph,
                                            const int*   __restrict__ pointer,
                                            float* __restrict__ out,
                                            int V, int Vext,
                                            int L_DEC, int L_SRC)
{
    extern __shared__ float srow[];
    int row = blockIdx.x;
    int b   = row / L_DEC;
    int t   = row - b * L_DEC;
    float pg = __ldg(&p_gen[row]);
    float one_m = 1.0f - pg;

    for (int i = threadIdx.x; i < Vext; i += blockDim.x)
        srow[i] = 0.f;
    __syncthreads();

    const float* arow = alph + ((size_t)b * L_SRC) * L_DEC + t;
    const int*   prow = pointer + b * L_SRC;
    for (int s = threadIdx.x; s < L_SRC; s += blockDim.x)
        atomicAdd(&srow[__ldg(&prow[s])], one_m * __ldg(&arow[(size_t)s * L_DEC]));
    __syncthreads();

    for (int i = threadIdx.x; i < Vext; i += blockDim.x) {
        float c = srow[i];
        if (i < V) c = fmaf(pg, __ldg(&dist[(size_t)row * V + i]), c);
        out[(size_t)row * Vext + i] = c;
    }
}

extern "C" void kernel_launch(void* const* d_in, const int* in_sizes, int n_in,
                              void* d_out, int out_size)
{
    // metadata order: dist_t, p_gen, alph_t, batch_vocab, pointer
    const float* dist    = (const float*)d_in[0];
    const float* p_gen   = (const float*)d_in[1];
    const float* alph    = (const float*)d_in[2];
    const int*   pointer = (const int*)d_in[4];
    float*       out     = (float*)d_out;

    int BT    = in_sizes[1];                 // B * L_DEC   (2048)
    int Vext  = in_sizes[3];                 // 32128
    int BS    = in_sizes[4];                 // B * L_SRC   (4096)
    int L_DEC = in_sizes[2] / BS;            // 256
    int B     = BT / L_DEC;                  // 8
    int L_SRC = BS / B;                      // 512
    int V     = in_sizes[0] / BT;            // 32000

    bool vec_ok = (V % 4 == 0) && (Vext % (4 * NCHUNK) == 0);

    if (vec_ok) {
        int V4     = V / 4;
        int Vext4  = Vext / 4;
        int chunk4 = Vext4 / NCHUNK;          // 1004 float4 per chunk
        copynet_stream_scatter_kernel<<<BT * NCHUNK, TPB>>>(
            dist, p_gen, alph, pointer, out, V4, Vext4, chunk4, L_DEC, L_SRC);
    } else {
        size_t smem_bytes = (size_t)Vext * sizeof(float);
        cudaFuncSetAttribute(copynet_fused_scalar_kernel,
                             cudaFuncAttributeMaxDynamicSharedMemorySize,
                             (int)smem_bytes);
        copynet_fused_scalar_kernel<<<BT, 1024, smem_bytes>>>(
            dist, p_gen, alph, pointer, out, V, Vext, L_DEC, L_SRC);
    }
}